// round 3
// baseline (speedup 1.0000x reference)
#include <cuda_runtime.h>

// NeuralCRF log-partition backward DP, one CTA per batch (B=64), T=128.
// Per step: Beta_i = m + log( sum_j exp(trans_ij) * exp(em_j + Beta_j - m) ).
// exp(trans) register-resident as packed f32x2 (64 x u64 per thread).
// Matvec uses fma.rn.f32x2 (SASS FFMA2): 64 packed FMAs instead of 128 FFMA.
// Shift m is 2-executed-steps stale (thread 0 writes it for step t+2 during
// step t; the step-t+1 barrier publishes it), so each step needs exactly ONE
// __syncthreads. u double-buffered by parity (the same barrier covers WAR).
// Staleness-safety: exponent stays within ~[-6, +11] (fp32-safe); exact
// block logsumexp only at the very end.

#define TDIM 128

typedef unsigned long long ull;

__device__ __forceinline__ ull pk2(float a, float b) {
    ull r;
    asm("mov.b64 %0, {%1,%2};" : "=l"(r) : "f"(a), "f"(b));
    return r;
}
__device__ __forceinline__ void upk2(float& a, float& b, ull v) {
    asm("mov.b64 {%0,%1}, %2;" : "=f"(a), "=f"(b) : "l"(v));
}
__device__ __forceinline__ void fma2(ull& acc, ull a, ull b) {
    asm("fma.rn.f32x2 %0, %1, %2, %0;" : "+l"(acc) : "l"(a), "l"(b));
}
__device__ __forceinline__ void add2(ull& acc, ull a) {
    asm("add.rn.f32x2 %0, %0, %1;" : "+l"(acc) : "l"(a));
}

__global__ __launch_bounds__(TDIM, 1)
void crf_logz_kernel(const int* __restrict__ W,
                     const float* __restrict__ em,
                     const float* __restrict__ trans,
                     float* __restrict__ out,
                     int S)
{
    const int b = blockIdx.x;
    const int i = threadIdx.x;

    __shared__ __align__(16) float u_sm[2][TDIM];
    __shared__ float m_sm[2];
    __shared__ float red_sm[8];

    // ---- E row i = exp(trans[i,:]) packed into 64 x f32x2 registers ----
    ull e2[TDIM / 2];
    {
        const float4* trow = reinterpret_cast<const float4*>(trans + i * TDIM);
#pragma unroll
        for (int j4 = 0; j4 < TDIM / 4; ++j4) {
            float4 t4 = __ldg(trow + j4);
            e2[2 * j4 + 0] = pk2(__expf(t4.x), __expf(t4.y));
            e2[2 * j4 + 1] = pk2(__expf(t4.z), __expf(t4.w));
        }
    }
    const float trans_bot = __ldg(trans + 1 * TDIM + i);  // trans[BOT_IDX=1, i]

    const float* emb = em + (size_t)b * (size_t)S * TDIM;
    const int*   Wb  = W  + (size_t)b * (size_t)S;

    float Beta = 0.0f;
    if (i == 0) { m_sm[0] = 3.5f; m_sm[1] = 11.0f; }

    // distance-2 prefetch of emission row + word id
    float eA = emb[(size_t)(S - 1) * TDIM + i];
    float eB = emb[(size_t)(S - 2) * TDIM + i];
    int   wA = Wb[S - 1];
    int   wB = Wb[S - 2];

    int p = 0;  // parity over EXECUTED steps
    __syncthreads();

    for (int r = S - 1; r >= 1; --r) {
        int rp = r - 2;
        rp = rp < 0 ? 0 : rp;               // r==1 prefetches row 0 (final)
        float eC = emb[(size_t)rp * TDIM + i];
        int   wC = Wb[rp];

        if ((wA != 0) & (wA != 3)) {        // mask uniform across block
            float m = m_sm[p];              // written 2 executed-steps ago
            u_sm[p][i] = __expf(eA + Beta - m);
            __syncthreads();                // the ONLY barrier per step

            ull acc[8];
#pragma unroll
            for (int k = 0; k < 8; ++k) acc[k] = 0ull;

            const ulonglong2* u2p =
                reinterpret_cast<const ulonglong2*>(u_sm[p]);
#pragma unroll
            for (int k = 0; k < TDIM / 4; ++k) {   // 32 x LDS.128, ALL 128 u's
                ulonglong2 uv = u2p[k];            // floats [4k, 4k+4)
                fma2(acc[(2 * k)     & 7], e2[2 * k],     uv.x);
                fma2(acc[(2 * k + 1) & 7], e2[2 * k + 1], uv.y);
            }
            add2(acc[0], acc[4]);
            add2(acc[1], acc[5]);
            add2(acc[2], acc[6]);
            add2(acc[3], acc[7]);
            add2(acc[0], acc[2]);
            add2(acc[1], acc[3]);
            add2(acc[0], acc[1]);
            float s0, s1;
            upk2(s0, s1, acc[0]);

            Beta = m + __logf(s0 + s1);
            // shift for step t+2 (published by next step's barrier);
            // +8 centers the typical 2-step growth (~[7, 14])
            if (i == 0) m_sm[p] = Beta + 8.0f;
            p ^= 1;
        }

        eA = eB; wA = wB;
        eB = eC; wB = wC;
    }

    // ---- logZ = lse_i( trans[BOT,i] + em[b,0,i] + Beta_i ), exact ----
    float f = trans_bot + eA + Beta;

    float mv = f;
#pragma unroll
    for (int o = 16; o > 0; o >>= 1)
        mv = fmaxf(mv, __shfl_xor_sync(0xffffffffu, mv, o));
    if ((i & 31) == 0) red_sm[i >> 5] = mv;
    __syncthreads();
    float mm = fmaxf(fmaxf(red_sm[0], red_sm[1]), fmaxf(red_sm[2], red_sm[3]));

    float s = __expf(f - mm);
#pragma unroll
    for (int o = 16; o > 0; o >>= 1)
        s += __shfl_xor_sync(0xffffffffu, s, o);
    if ((i & 31) == 0) red_sm[4 + (i >> 5)] = s;
    __syncthreads();

    if (i == 0) {
        float tot = (red_sm[4] + red_sm[5]) + (red_sm[6] + red_sm[7]);
        out[b] = mm + __logf(tot);
    }
}

extern "C" void kernel_launch(void* const* d_in, const int* in_sizes, int n_in,
                              void* d_out, int out_size)
{
    const int*   W     = (const int*)d_in[0];
    const float* em    = (const float*)d_in[1];
    const float* trans = (const float*)d_in[2];
    float*       out   = (float*)d_out;

    const int B = out_size;            // 64
    const int S = in_sizes[0] / B;     // 1024

    crf_logz_kernel<<<B, TDIM>>>(W, em, trans, out, S);
}